// round 1
// baseline (speedup 1.0000x reference)
#include <cuda_runtime.h>
#include <math_constants.h>

// Problem constants (B,C,D,H,W) = (4,8,16,256,256), k=3, stride=1, pad=1
#define BC   32
#define DD   16
#define HH   256
#define WW   256
#define HW   (HH*WW)
#define CHV  (DD*HW)          // elems per channel volume = 1,048,576

#define TH   16
#define TW   32
#define TROW (TW+2)           // 34
#define TS   ((TH+2)*TROW)    // 612
#define NTHREADS (TH*TW)      // 512

__device__ unsigned int g_max_u[BC];

__device__ __forceinline__ unsigned int flip_f(float f) {
    unsigned int u = __float_as_uint(f);
    return u ^ ((unsigned int)(((int)u) >> 31) | 0x80000000u);
}
__device__ __forceinline__ float unflip_f(unsigned int u) {
    unsigned int m = (u & 0x80000000u) ? 0x80000000u : 0xFFFFFFFFu;
    return __uint_as_float(u ^ m);
}

__global__ void init_max_kernel() {
    if (threadIdx.x < BC) g_max_u[threadIdx.x] = 0x007FFFFFu; // flip(-inf)
}

__global__ void channel_max_kernel(const float* __restrict__ x) {
    const int ch = blockIdx.x;
    const float4* p = (const float4*)(x + (size_t)ch * CHV);
    const int nvec = CHV / 4;
    float m = -CUDART_INF_F;
    for (int i = blockIdx.y * blockDim.x + threadIdx.x; i < nvec;
         i += gridDim.y * blockDim.x) {
        float4 v = p[i];
        m = fmaxf(m, fmaxf(fmaxf(v.x, v.y), fmaxf(v.z, v.w)));
    }
    #pragma unroll
    for (int o = 16; o; o >>= 1) m = fmaxf(m, __shfl_xor_sync(0xFFFFFFFFu, m, o));
    __shared__ float sm[8];
    if ((threadIdx.x & 31) == 0) sm[threadIdx.x >> 5] = m;
    __syncthreads();
    if (threadIdx.x == 0) {
        float bm = sm[0];
        #pragma unroll
        for (int i = 1; i < 8; i++) bm = fmaxf(bm, sm[i]);
        atomicMax(&g_max_u[ch], flip_f(bm));
    }
}

__global__ __launch_bounds__(NTHREADS)
void softargmax_kernel(const float* __restrict__ x, float* __restrict__ out) {
    const int bc = blockIdx.z;
    const int h0 = blockIdx.y * TH;
    const int w0 = blockIdx.x * TW;
    const int tid = threadIdx.x;
    const int tx = tid & 31;
    const int ty = tid >> 5;

    __shared__ float2 tile[TS];

    const float mx = unflip_f(g_max_u[bc]);
    const float* __restrict__ xc = x + (size_t)bc * CHV;

    float* __restrict__ coords = out;                       // (BC,3,D,H,W)
    float* __restrict__ vals   = out + (size_t)BC * 3 * CHV;

    // rolling per-slice window sums: prev / cur / next
    float p0 = 0.f, px = 0.f, py = 0.f, pv = 0.f;
    float c0 = 0.f, cx = 0.f, cy = 0.f, cv = 0.f;

    // ---- load slice 0 ----
    {
        const float* xs = xc; // z = 0
        for (int i = tid; i < TS; i += NTHREADS) {
            int hh = i / TROW + h0 - 1;
            int ww = i % TROW + w0 - 1;
            float2 v = make_float2(0.f, 0.f);
            if (hh >= 0 && hh < HH && ww >= 0 && ww < WW) {
                float xv = __ldg(xs + hh * WW + ww);
                float e = __expf(xv - mx);
                v = make_float2(e, e * xv);
            }
            tile[i] = v;
        }
        __syncthreads();
        // slice sums for z=0 -> cur
        #pragma unroll
        for (int r = 0; r < 3; r++) {
            float2 a = tile[(ty + r) * TROW + tx + 0];
            float2 b = tile[(ty + r) * TROW + tx + 1];
            float2 c = tile[(ty + r) * TROW + tx + 2];
            float rs = a.x + b.x + c.x;
            c0 += rs;
            cx += c.x - a.x;
            if (r == 0) cy -= rs;
            if (r == 2) cy += rs;
            cv += a.y + b.y + c.y;
        }
    }

    const int h = h0 + ty;
    const int w = w0 + tx;
    const size_t pixbase = (size_t)h * WW + w;
    const size_t bc_coord = (size_t)bc * 3 * CHV;
    const size_t bc_vals  = (size_t)bc * CHV;

    for (int d = 0; d < DD; d++) {
        float n0 = 0.f, nx = 0.f, ny = 0.f, nv = 0.f;
        if (d + 1 < DD) {
            __syncthreads();  // prior compute done before tile overwrite
            const float* xs = xc + (size_t)(d + 1) * HW;
            for (int i = tid; i < TS; i += NTHREADS) {
                int hh = i / TROW + h0 - 1;
                int ww = i % TROW + w0 - 1;
                float2 v = make_float2(0.f, 0.f);
                if (hh >= 0 && hh < HH && ww >= 0 && ww < WW) {
                    float xv = __ldg(xs + hh * WW + ww);
                    float e = __expf(xv - mx);
                    v = make_float2(e, e * xv);
                }
                tile[i] = v;
            }
            __syncthreads();
            #pragma unroll
            for (int r = 0; r < 3; r++) {
                float2 a = tile[(ty + r) * TROW + tx + 0];
                float2 b = tile[(ty + r) * TROW + tx + 1];
                float2 c = tile[(ty + r) * TROW + tx + 2];
                float rs = a.x + b.x + c.x;
                n0 += rs;
                nx += c.x - a.x;
                if (r == 0) ny -= rs;
                if (r == 2) ny += rs;
                nv += a.y + b.y + c.y;
            }
        }

        const float den = p0 + c0 + n0 + 1e-8f;
        const float inv = 1.0f / den;
        const size_t base = (size_t)d * HW + pixbase;

        coords[bc_coord + 0 * (size_t)CHV + base] = (float)d + (n0 - p0) * inv;
        coords[bc_coord + 1 * (size_t)CHV + base] = (float)w + (px + cx + nx) * inv;
        coords[bc_coord + 2 * (size_t)CHV + base] = (float)h + (py + cy + ny) * inv;
        vals[bc_vals + base] = (pv + cv + nv) * inv;

        p0 = c0; px = cx; py = cy; pv = cv;
        c0 = n0; cx = nx; cy = ny; cv = nv;
    }
}

extern "C" void kernel_launch(void* const* d_in, const int* in_sizes, int n_in,
                              void* d_out, int out_size) {
    const float* x = (const float*)d_in[0];
    float* out = (float*)d_out;

    init_max_kernel<<<1, BC>>>();
    channel_max_kernel<<<dim3(BC, 32), 256>>>(x);
    softargmax_kernel<<<dim3(WW / TW, HH / TH, BC), NTHREADS>>>(x, out);
}

// round 2
// speedup vs baseline: 1.5211x; 1.5211x over previous
#include <cuda_runtime.h>

// (B,C,D,H,W) = (4,8,16,256,256), k=3, stride=1, pad=1
#define BC   32
#define DD   16
#define HH   256
#define WW   256
#define HW   (HH*WW)
#define CHV  (DD*HW)          // 1,048,576 elems per (b,c) volume

#define TH    16              // tile height (pixels)
#define TXN   32              // threads in x
#define TWPIX 64              // tile width in pixels (2 px / thread)
#define ROWS  (TH+2)          // 18
#define COLS  (TWPIX+2)       // 66
#define TS    (ROWS*COLS)     // 1188
#define NT    (TH*TXN)        // 512 threads

__global__ __launch_bounds__(NT)
void softargmax_kernel(const float* __restrict__ x, float* __restrict__ out)
{
    const int bc = blockIdx.z;
    const int h0 = blockIdx.y * TH;
    const int w0 = blockIdx.x * TWPIX;
    const int tid = threadIdx.x;
    const int tx = tid & 31;
    const int ty = tid >> 5;

    __shared__ __align__(16) float2 tile[TS];  // (e, e*x) for one z-slice + halo

    const float* __restrict__ xc = x + (size_t)bc * CHV;

    // --- precompute the (slice-invariant) halo load slots for this thread ---
    int  off[3];
    bool inr[3], pred[3];
    #pragma unroll
    for (int j = 0; j < 3; j++) {
        int i = tid + j * NT;
        int r = i / COLS, c = i % COLS;
        int hh = h0 + r - 1, ww = w0 + c - 1;
        inr[j]  = (i < TS);
        pred[j] = inr[j] && (hh >= 0) && (hh < HH) && (ww >= 0) && (ww < WW);
        off[j]  = pred[j] ? hh * WW + ww : 0;
    }

    float rv[3];  // pipelined raw loads for the next slice

    // load slice 0
    #pragma unroll
    for (int j = 0; j < 3; j++) rv[j] = pred[j] ? __ldg(xc + off[j]) : 0.f;

    // publish rv (exp'ed) into the shared tile
    #define PUBLISH()                                                        \
        _Pragma("unroll")                                                    \
        for (int j = 0; j < 3; j++) {                                        \
            int i = tid + j * NT;                                            \
            if (inr[j]) {                                                    \
                float e = pred[j] ? __expf(rv[j]) : 0.f;                     \
                tile[i] = make_float2(e, e * rv[j]);                         \
            }                                                                \
        }

    // accumulate this slice's window sums for both pixels into s[8]:
    // s[0..3] = {sum, xnum, ynum, vnum} for px0; s[4..7] same for px1
    #define ACCUM(s)                                                         \
        _Pragma("unroll")                                                    \
        for (int r = 0; r < 3; r++) {                                        \
            const float4 A = *reinterpret_cast<const float4*>(               \
                &tile[(ty + r) * COLS + 2 * tx]);                            \
            const float4 B = *reinterpret_cast<const float4*>(               \
                &tile[(ty + r) * COLS + 2 * tx + 2]);                        \
            float rs0 = A.x + A.z + B.x;                                     \
            float rs1 = A.z + B.x + B.z;                                     \
            (s)[0] += rs0;          (s)[4] += rs1;                           \
            (s)[1] += B.x - A.x;    (s)[5] += B.z - A.z;                     \
            if (r == 0) { (s)[2] -= rs0; (s)[6] -= rs1; }                    \
            if (r == 2) { (s)[2] += rs0; (s)[6] += rs1; }                    \
            (s)[3] += A.y + A.w + B.y;                                       \
            (s)[7] += A.w + B.y + B.w;                                       \
        }

    float p[8], c[8], n[8];
    #pragma unroll
    for (int k = 0; k < 8; k++) { p[k] = 0.f; c[k] = 0.f; }

    PUBLISH();                 // slice 0 -> shared
    __syncthreads();
    #pragma unroll
    for (int j = 0; j < 3; j++) rv[j] = pred[j] ? __ldg(xc + HW + off[j]) : 0.f; // prefetch slice 1
    ACCUM(c);                  // c = sums(slice 0)

    const int h = h0 + ty;
    const int w = w0 + 2 * tx;
    float* __restrict__ coords = out + (size_t)bc * 3 * CHV;
    float* __restrict__ vals   = out + (size_t)BC * 3 * CHV + (size_t)bc * CHV;
    const size_t pixbase = (size_t)h * WW + w;

    #pragma unroll 1
    for (int d = 0; d < DD; d++) {
        #pragma unroll
        for (int k = 0; k < 8; k++) n[k] = 0.f;

        if (d + 1 < DD) {
            __syncthreads();   // all reads of tile (prev ACCUM) done
            PUBLISH();         // slice d+1 -> shared
            __syncthreads();
            if (d + 2 < DD) {  // prefetch slice d+2 (hidden behind ACCUM + stores)
                const float* xs2 = xc + (size_t)(d + 2) * HW;
                #pragma unroll
                for (int j = 0; j < 3; j++) rv[j] = pred[j] ? __ldg(xs2 + off[j]) : 0.f;
            }
            ACCUM(n);          // n = sums(slice d+1)
        }

        const float inv0 = 1.0f / (p[0] + c[0] + n[0] + 1e-8f);
        const float inv1 = 1.0f / (p[4] + c[4] + n[4] + 1e-8f);
        const size_t base = (size_t)d * HW + pixbase;

        float2 z2 = make_float2((float)d + (n[0] - p[0]) * inv0,
                                (float)d + (n[4] - p[4]) * inv1);
        float2 x2 = make_float2((float)w       + (p[1] + c[1] + n[1]) * inv0,
                                (float)(w + 1) + (p[5] + c[5] + n[5]) * inv1);
        float2 y2 = make_float2((float)h + (p[2] + c[2] + n[2]) * inv0,
                                (float)h + (p[6] + c[6] + n[6]) * inv1);
        float2 v2 = make_float2((p[3] + c[3] + n[3]) * inv0,
                                (p[7] + c[7] + n[7]) * inv1);

        __stcs(reinterpret_cast<float2*>(coords + base), z2);
        __stcs(reinterpret_cast<float2*>(coords + (size_t)CHV + base), x2);
        __stcs(reinterpret_cast<float2*>(coords + 2 * (size_t)CHV + base), y2);
        __stcs(reinterpret_cast<float2*>(vals + base), v2);

        #pragma unroll
        for (int k = 0; k < 8; k++) { p[k] = c[k]; c[k] = n[k]; }
    }
}

extern "C" void kernel_launch(void* const* d_in, const int* in_sizes, int n_in,
                              void* d_out, int out_size) {
    const float* x = (const float*)d_in[0];
    float* out = (float*)d_out;
    softargmax_kernel<<<dim3(WW / TWPIX, HH / TH, BC), NT>>>(x, out);
}

// round 3
// speedup vs baseline: 1.6315x; 1.0726x over previous
#include <cuda_runtime.h>

// (B,C,D,H,W) = (4,8,16,256,256), k=3, stride=1, pad=1
#define BC   32
#define DD   16
#define HH   256
#define WW   256
#define HW   (HH*WW)
#define CHV  (DD*HW)

#define TH    16              // tile height
#define TXN   32              // threads in x
#define TWPIX 64              // tile width in pixels (2 px / thread)
#define ROWS  (TH+2)          // 18
#define COLS  (TWPIX+2)       // 66
#define TS    (ROWS*COLS)     // 1188
#define NT    (TH*TXN)        // 512

__global__ void __launch_bounds__(NT, 2)
softargmax_kernel(const float* __restrict__ x, float* __restrict__ out)
{
    const int bc = blockIdx.z;
    const int h0 = blockIdx.y * TH;
    const int w0 = blockIdx.x * TWPIX;
    const int tid = threadIdx.x;
    const int tx = tid & 31;
    const int ty = tid >> 5;

    // double-buffered (e, e*x) slice tiles
    __shared__ __align__(16) float2 tile[2][TS];

    const float* __restrict__ xc = x + (size_t)bc * CHV;

    // slice-invariant halo load slots
    int  off[3];
    bool inr[3], pred[3];
    #pragma unroll
    for (int j = 0; j < 3; j++) {
        int i = tid + j * NT;
        int r = i / COLS, c = i % COLS;
        int hh = h0 + r - 1, ww = w0 + c - 1;
        inr[j]  = (i < TS);
        pred[j] = inr[j] && (hh >= 0) && (hh < HH) && (ww >= 0) && (ww < WW);
        off[j]  = pred[j] ? hh * WW + ww : 0;
    }

    float rv[3];
    #pragma unroll
    for (int j = 0; j < 3; j++) rv[j] = pred[j] ? __ldg(xc + off[j]) : 0.f;

    #define PUBLISH(BUF)                                                     \
        _Pragma("unroll")                                                    \
        for (int j = 0; j < 3; j++) {                                        \
            int i = tid + j * NT;                                            \
            if (inr[j]) {                                                    \
                float e = pred[j] ? __expf(rv[j]) : 0.f;                     \
                tile[BUF][i] = make_float2(e, e * rv[j]);                    \
            }                                                                \
        }

    // s[0..3]={sum,xnum,ynum,vnum} px0 ; s[4..7] px1
    #define ACCUM(s, BUF)                                                    \
        _Pragma("unroll")                                                    \
        for (int r = 0; r < 3; r++) {                                        \
            const float4 A = *reinterpret_cast<const float4*>(               \
                &tile[BUF][(ty + r) * COLS + 2 * tx]);                       \
            const float4 B = *reinterpret_cast<const float4*>(               \
                &tile[BUF][(ty + r) * COLS + 2 * tx + 2]);                   \
            float rs0 = A.x + A.z + B.x;                                     \
            float rs1 = A.z + B.x + B.z;                                     \
            (s)[0] += rs0;          (s)[4] += rs1;                           \
            (s)[1] += B.x - A.x;    (s)[5] += B.z - A.z;                     \
            if (r == 0) { (s)[2] -= rs0; (s)[6] -= rs1; }                    \
            if (r == 2) { (s)[2] += rs0; (s)[6] += rs1; }                    \
            (s)[3] += A.y + A.w + B.y;                                       \
            (s)[7] += A.w + B.y + B.w;                                       \
        }

    float p[8], c[8], n[8];
    #pragma unroll
    for (int k = 0; k < 8; k++) { p[k] = 0.f; c[k] = 0.f; }

    // prologue: slice 0 -> buf0
    PUBLISH(0);
    #pragma unroll
    for (int j = 0; j < 3; j++) rv[j] = pred[j] ? __ldg(xc + HW + off[j]) : 0.f;
    __syncthreads();
    ACCUM(c, 0);

    const int h = h0 + ty;
    const int w = w0 + 2 * tx;
    float* __restrict__ coords = out + (size_t)bc * 3 * CHV;
    float* __restrict__ vals   = out + (size_t)BC * 3 * CHV + (size_t)bc * CHV;
    const size_t pixbase = (size_t)h * WW + w;

    #pragma unroll
    for (int d = 0; d < DD; d++) {
        #pragma unroll
        for (int k = 0; k < 8; k++) n[k] = 0.f;

        if (d + 1 < DD) {
            const int buf = (d + 1) & 1;
            PUBLISH(buf);                       // slice d+1
            if (d + 2 < DD) {                   // prefetch slice d+2
                const float* xs2 = xc + (size_t)(d + 2) * HW;
                #pragma unroll
                for (int j = 0; j < 3; j++)
                    rv[j] = pred[j] ? __ldg(xs2 + off[j]) : 0.f;
            }
            __syncthreads();                    // single barrier per slice
            ACCUM(n, buf);
        }

        const float inv0 = __fdividef(1.0f, p[0] + c[0] + n[0] + 1e-8f);
        const float inv1 = __fdividef(1.0f, p[4] + c[4] + n[4] + 1e-8f);
        const size_t base = (size_t)d * HW + pixbase;

        float2 z2 = make_float2((float)d + (n[0] - p[0]) * inv0,
                                (float)d + (n[4] - p[4]) * inv1);
        float2 x2 = make_float2((float)w       + (p[1] + c[1] + n[1]) * inv0,
                                (float)(w + 1) + (p[5] + c[5] + n[5]) * inv1);
        float2 y2 = make_float2((float)h + (p[2] + c[2] + n[2]) * inv0,
                                (float)h + (p[6] + c[6] + n[6]) * inv1);
        float2 v2 = make_float2((p[3] + c[3] + n[3]) * inv0,
                                (p[7] + c[7] + n[7]) * inv1);

        __stcs(reinterpret_cast<float2*>(coords + base), z2);
        __stcs(reinterpret_cast<float2*>(coords + (size_t)CHV + base), x2);
        __stcs(reinterpret_cast<float2*>(coords + 2 * (size_t)CHV + base), y2);
        __stcs(reinterpret_cast<float2*>(vals + base), v2);

        #pragma unroll
        for (int k = 0; k < 8; k++) { p[k] = c[k]; c[k] = n[k]; }
    }
}

extern "C" void kernel_launch(void* const* d_in, const int* in_sizes, int n_in,
                              void* d_out, int out_size) {
    const float* x = (const float*)d_in[0];
    float* out = (float*)d_out;
    softargmax_kernel<<<dim3(WW / TWPIX, HH / TH, BC), NT>>>(x, out);
}